// round 11
// baseline (speedup 1.0000x reference)
#include <cuda_runtime.h>
#include <math.h>

#define MAXN 100000
#define MAXE 1000000
#define MAXG 128
#define HDIM 64

typedef unsigned long long u64;

// ---------------- f32x2 packed helpers ----------------
__device__ __forceinline__ u64 pack2(float lo, float hi) {
    u64 r; asm("mov.b64 %0, {%1, %2};" : "=l"(r) : "f"(lo), "f"(hi)); return r;
}
__device__ __forceinline__ void unpack2(float& lo, float& hi, u64 v) {
    asm("mov.b64 {%0, %1}, %2;" : "=f"(lo), "=f"(hi) : "l"(v));
}
__device__ __forceinline__ void fma2(u64& acc, u64 a, u64 b) {
    asm("fma.rn.f32x2 %0, %1, %2, %0;" : "+l"(acc) : "l"(a), "l"(b));
}

// ---------------- device scratch ----------------
__device__ float g_x[MAXN * HDIM];
__device__ int   g_indeg[MAXN + 1];
__device__ int   g_off[MAXN + 1];
__device__ int   g_cursor[MAXN];
__device__ int   g_csr[MAXE];
__device__ int   g_bsum[1024];
__device__ float g_pooled[4 * MAXG * HDIM];
__device__ int   g_cnt[MAXG];

// ---------------- small kernels ----------------
__global__ void k_zero(int n_indeg) {
    int i = blockIdx.x * blockDim.x + threadIdx.x;
    if (i < 4 * MAXG * HDIM) g_pooled[i] = 0.f;
    if (i < MAXG) g_cnt[i] = 0;
    if (i < n_indeg) g_indeg[i] = 0;
}

// degree count + per-graph node count in one launch
__global__ void k_count(const int* __restrict__ dst, const int* __restrict__ batch,
                        int E, int N) {
    int e = blockIdx.x * blockDim.x + threadIdx.x;
    if (e < E) atomicAdd(&g_indeg[dst[e]], 1);
    if (e < N) atomicAdd(&g_cnt[batch[e]], 1);
}

__global__ void k_scan1(int n) {
    __shared__ int s[1024];
    int i = blockIdx.x * 1024 + threadIdx.x;
    int v = (i < n) ? g_indeg[i] : 0;
    s[threadIdx.x] = v; __syncthreads();
    for (int d = 1; d < 1024; d <<= 1) {
        int t = (threadIdx.x >= d) ? s[threadIdx.x - d] : 0;
        __syncthreads(); s[threadIdx.x] += t; __syncthreads();
    }
    if (i < n) g_cursor[i] = s[threadIdx.x];
    if (threadIdx.x == 1023) g_bsum[blockIdx.x] = s[1023];
}
__global__ void k_scan2(int nb) {
    __shared__ int s[1024];
    int v = (threadIdx.x < nb) ? g_bsum[threadIdx.x] : 0;
    s[threadIdx.x] = v; __syncthreads();
    for (int d = 1; d < 1024; d <<= 1) {
        int t = (threadIdx.x >= d) ? s[threadIdx.x - d] : 0;
        __syncthreads(); s[threadIdx.x] += t; __syncthreads();
    }
    if (threadIdx.x < nb) g_bsum[threadIdx.x] = s[threadIdx.x];
}
__global__ void k_scan3(int n, int nb) {
    int i = blockIdx.x * blockDim.x + threadIdx.x;
    if (i < n) {
        int blk = i >> 10;
        int pref = (blk > 0) ? g_bsum[blk - 1] : 0;
        int excl = g_cursor[i] - g_indeg[i] + pref;
        g_off[i] = excl; g_cursor[i] = excl;
    }
    if (i == 0) g_off[n] = g_bsum[nb - 1];
}
__global__ void k_fill(const int* __restrict__ src, const int* __restrict__ dst, int E) {
    int e = blockIdx.x * blockDim.x + threadIdx.x;
    if (e < E) { int pos = atomicAdd(&g_cursor[dst[e]], 1); g_csr[pos] = src[e]; }
}

// ---------------- embed MLP: 64-node tile (unchanged structure, BN folded into W) ----------------
__global__ void __launch_bounds__(256) k_mlp_embed(
    const float* __restrict__ emb, const int* __restrict__ node_ids,
    const float* __restrict__ W1, const float* __restrict__ B1,
    const float* __restrict__ G1, const float* __restrict__ BT1,
    const float* __restrict__ M1, const float* __restrict__ V1,
    const float* __restrict__ W2, const float* __restrict__ B2,
    const float* __restrict__ G2, const float* __restrict__ BT2,
    const float* __restrict__ M2, const float* __restrict__ V2,
    const int* __restrict__ batch, int N)
{
    const int IN = 128;
    extern __shared__ float sm[];
    float* W1s = sm;                 // IN*64
    float* W2s = W1s + IN * 64;      // 64*64
    float* Xs  = W2s + 64 * 64;      // IN*68
    float* Hs  = Xs + IN * 68;       // 64*68
    float* sc1 = Hs + 64 * 68;
    float* of1 = sc1 + 64;
    float* sc2 = of1 + 64;
    float* of2 = sc2 + 64;

    int tid = threadIdx.x;
    int base = blockIdx.x * 64;

    if (tid < 64) {
        float s = G1[tid] * rsqrtf(V1[tid] + 1e-5f);
        sc1[tid] = s;
        of1[tid] = B1[tid] * s + BT1[tid] - M1[tid] * s;
        float s2 = G2[tid] * rsqrtf(V2[tid] + 1e-5f);
        sc2[tid] = s2;
        of2[tid] = B2[tid] * s2 + BT2[tid] - M2[tid] * s2;
    }
    __syncthreads();

    for (int i = tid; i < IN * 64; i += 256) W1s[i] = W1[i] * sc1[i & 63];
    for (int i = tid; i < 64 * 64; i += 256) W2s[i] = W2[i] * sc2[i & 63];

    // stage input tile transposed into Xs[k][n]
    {
        int n = tid >> 2, q = tid & 3;
        int node = base + n;
        const float4* row = (node < N)
            ? (const float4*)(emb + (size_t)__ldg(&node_ids[node]) * 128) : 0;
#pragma unroll
        for (int i = 0; i < 8; i++) {
            float4 v = make_float4(0.f, 0.f, 0.f, 0.f);
            if (node < N) v = __ldg(&row[q * 8 + i]);
            int k = (q * 8 + i) * 4;
            Xs[(k + 0) * 68 + n] = v.x;
            Xs[(k + 1) * 68 + n] = v.y;
            Xs[(k + 2) * 68 + n] = v.z;
            Xs[(k + 3) * 68 + n] = v.w;
        }
    }
    __syncthreads();

    int tj = tid & 15, tn = tid >> 4;
    int nb = tn * 4, jb = tj * 4;
    u64 acc2[4][2];
#pragma unroll
    for (int u = 0; u < 4; u++) { acc2[u][0] = 0ULL; acc2[u][1] = 0ULL; }

#pragma unroll 4
    for (int k = 0; k < IN; k++) {
        float4 a = *(const float4*)(Xs + k * 68 + nb);
        float4 b = *(const float4*)(W1s + k * 64 + jb);
        u64 b0 = pack2(b.x, b.y), b1 = pack2(b.z, b.w);
        u64 a0 = pack2(a.x, a.x), a1 = pack2(a.y, a.y);
        u64 a2 = pack2(a.z, a.z), a3 = pack2(a.w, a.w);
        fma2(acc2[0][0], a0, b0); fma2(acc2[0][1], a0, b1);
        fma2(acc2[1][0], a1, b0); fma2(acc2[1][1], a1, b1);
        fma2(acc2[2][0], a2, b0); fma2(acc2[2][1], a2, b1);
        fma2(acc2[3][0], a3, b0); fma2(acc2[3][1], a3, b1);
    }
#pragma unroll
    for (int p = 0; p < 2; p++) {
        float o0 = of1[jb + 2 * p], o1 = of1[jb + 2 * p + 1];
#pragma unroll
        for (int u = 0; u < 4; u++) {
            float lo, hi;
            unpack2(lo, hi, acc2[u][p]);
            Hs[(jb + 2 * p) * 68 + nb + u]     = fmaxf(lo + o0, 0.f);
            Hs[(jb + 2 * p + 1) * 68 + nb + u] = fmaxf(hi + o1, 0.f);
            acc2[u][p] = 0ULL;
        }
    }
    __syncthreads();

#pragma unroll 4
    for (int k = 0; k < 64; k++) {
        float4 a = *(const float4*)(Hs + k * 68 + nb);
        float4 b = *(const float4*)(W2s + k * 64 + jb);
        u64 b0 = pack2(b.x, b.y), b1 = pack2(b.z, b.w);
        u64 a0 = pack2(a.x, a.x), a1 = pack2(a.y, a.y);
        u64 a2 = pack2(a.z, a.z), a3 = pack2(a.w, a.w);
        fma2(acc2[0][0], a0, b0); fma2(acc2[0][1], a0, b1);
        fma2(acc2[1][0], a1, b0); fma2(acc2[1][1], a1, b1);
        fma2(acc2[2][0], a2, b0); fma2(acc2[2][1], a2, b1);
        fma2(acc2[3][0], a3, b0); fma2(acc2[3][1], a3, b1);
    }
    __syncthreads();

    float* Os = Hs;
#pragma unroll
    for (int p = 0; p < 2; p++) {
        float o0 = of2[jb + 2 * p], o1 = of2[jb + 2 * p + 1];
#pragma unroll
        for (int u = 0; u < 4; u++) {
            float lo, hi;
            unpack2(lo, hi, acc2[u][p]);
            Os[(nb + u) * 68 + jb + 2 * p]     = fmaxf(lo + o0, 0.f);
            Os[(nb + u) * 68 + jb + 2 * p + 1] = fmaxf(hi + o1, 0.f);
        }
    }
    __syncthreads();

    {
        int n = tid >> 2, q = tid & 3;
        int node = base + n;
        if (node < N) {
#pragma unroll
            for (int i = 0; i < 4; i++) {
                float4 vv = *(const float4*)(Os + n * 68 + q * 16 + i * 4);
                *(float4*)(g_x + (size_t)node * 64 + q * 16 + i * 4) = vv;
            }
        }
    }

    // pooling (sorted batch, running-sum flush)
    if (tid < 64) {
        int rows = min(64, N - base);
        float* pool = g_pooled;  // poolIdx 0
        int cur = __ldg(&batch[base]);
        float s = 0.f;
        for (int r = 0; r < rows; r++) {
            int b = __ldg(&batch[base + r]);
            if (b != cur) { atomicAdd(&pool[cur * 64 + tid], s); s = 0.f; cur = b; }
            s += Os[r * 68 + tid];
        }
        atomicAdd(&pool[cur * 64 + tid], s);
    }
}

// ---------------- fused conv: CSR gather + 2-layer MLP + pool ----------------
// Block: 256 threads, 128 nodes x 64 out, 4 nodes x 8 outputs per thread.
__global__ void __launch_bounds__(256) k_conv(
    const float* __restrict__ W1, const float* __restrict__ B1,
    const float* __restrict__ G1, const float* __restrict__ BT1,
    const float* __restrict__ M1, const float* __restrict__ V1,
    const float* __restrict__ W2, const float* __restrict__ B2,
    const float* __restrict__ G2, const float* __restrict__ BT2,
    const float* __restrict__ M2, const float* __restrict__ V2,
    const int* __restrict__ batch, int poolIdx, int N)
{
    extern __shared__ float sm[];
    float* W1s = sm;                 // 64*64
    float* W2s = W1s + 64 * 64;      // 64*64
    float* Xs  = W2s + 64 * 64;      // 64*132  (transposed [k][node])
    float* Hs  = Xs + 64 * 132;      // max(64*132, 128*68) = 8704 floats
    float* cst = Hs + 8704;          // sc1, of1, sc2, of2 (4*64)

    int tid = threadIdx.x;
    int base = blockIdx.x * 128;

    if (tid < 64) {
        float s = G1[tid] * rsqrtf(V1[tid] + 1e-5f);
        cst[tid] = s;
        cst[64 + tid] = B1[tid] * s + BT1[tid] - M1[tid] * s;
        float s2 = G2[tid] * rsqrtf(V2[tid] + 1e-5f);
        cst[128 + tid] = s2;
        cst[192 + tid] = B2[tid] * s2 + BT2[tid] - M2[tid] * s2;
    }
    __syncthreads();

    for (int i = tid; i < 64 * 64; i += 256) W1s[i] = W1[i] * cst[i & 63];
    for (int i = tid; i < 64 * 64; i += 256) W2s[i] = W2[i] * cst[128 + (i & 63)];

    // fused gather: acc = x[node] + sum_{src->node} x[src]; 2 threads per node
    {
        int n = tid >> 1;            // 0..127
        int h = tid & 1;             // half: 32 floats
        int node = base + n;
        float acc[32];
#pragma unroll
        for (int c = 0; c < 32; c++) acc[c] = 0.f;
        if (node < N) {
            const float4* xr = (const float4*)(g_x + (size_t)node * 64 + h * 32);
#pragma unroll
            for (int i = 0; i < 8; i++) {
                float4 v = xr[i];
                acc[4 * i] = v.x; acc[4 * i + 1] = v.y; acc[4 * i + 2] = v.z; acc[4 * i + 3] = v.w;
            }
            int s = g_off[node], e = g_off[node + 1];
            for (int it = s; it < e; it++) {
                int sn = __ldg(&g_csr[it]);
                const float4* nr = (const float4*)(g_x + (size_t)sn * 64 + h * 32);
#pragma unroll
                for (int i = 0; i < 8; i++) {
                    float4 v = __ldg(&nr[i]);
                    acc[4 * i] += v.x; acc[4 * i + 1] += v.y;
                    acc[4 * i + 2] += v.z; acc[4 * i + 3] += v.w;
                }
            }
        }
#pragma unroll
        for (int c = 0; c < 32; c++) Xs[(h * 32 + c) * 132 + n] = acc[c];
    }
    __syncthreads();

    int tj = tid & 7, tn = tid >> 3;     // jb in 8s, nb in 4s
    int nb = tn * 4, jb = tj * 8;
    u64 acc2[4][4];
#pragma unroll
    for (int u = 0; u < 4; u++)
#pragma unroll
        for (int p = 0; p < 4; p++) acc2[u][p] = 0ULL;

    // layer 1
#pragma unroll 4
    for (int k = 0; k < 64; k++) {
        float4 a  = *(const float4*)(Xs + k * 132 + nb);
        float4 bl = *(const float4*)(W1s + k * 64 + jb);
        float4 bh = *(const float4*)(W1s + k * 64 + jb + 4);
        u64 B0 = pack2(bl.x, bl.y), B1p = pack2(bl.z, bl.w);
        u64 B2 = pack2(bh.x, bh.y), B3 = pack2(bh.z, bh.w);
        u64 A0 = pack2(a.x, a.x), A1 = pack2(a.y, a.y);
        u64 A2 = pack2(a.z, a.z), A3 = pack2(a.w, a.w);
        fma2(acc2[0][0], A0, B0); fma2(acc2[0][1], A0, B1p); fma2(acc2[0][2], A0, B2); fma2(acc2[0][3], A0, B3);
        fma2(acc2[1][0], A1, B0); fma2(acc2[1][1], A1, B1p); fma2(acc2[1][2], A1, B2); fma2(acc2[1][3], A1, B3);
        fma2(acc2[2][0], A2, B0); fma2(acc2[2][1], A2, B1p); fma2(acc2[2][2], A2, B2); fma2(acc2[2][3], A2, B3);
        fma2(acc2[3][0], A3, B0); fma2(acc2[3][1], A3, B1p); fma2(acc2[3][2], A3, B2); fma2(acc2[3][3], A3, B3);
    }
    // epilogue 1: BN(add)+ReLU -> Hs[k=j][n], rotated write order to spread banks
#pragma unroll
    for (int u = 0; u < 4; u++) {
        float vals[8];
#pragma unroll
        for (int p = 0; p < 4; p++) unpack2(vals[2 * p], vals[2 * p + 1], acc2[u][p]);
#pragma unroll
        for (int q = 0; q < 8; q++) {
            int qq = (q + tj) & 7;
            int j = jb + qq;
            Hs[j * 132 + nb + u] = fmaxf(vals[qq] + cst[64 + j], 0.f);
        }
    }
#pragma unroll
    for (int u = 0; u < 4; u++)
#pragma unroll
        for (int p = 0; p < 4; p++) acc2[u][p] = 0ULL;
    __syncthreads();

    // layer 2
#pragma unroll 4
    for (int k = 0; k < 64; k++) {
        float4 a  = *(const float4*)(Hs + k * 132 + nb);
        float4 bl = *(const float4*)(W2s + k * 64 + jb);
        float4 bh = *(const float4*)(W2s + k * 64 + jb + 4);
        u64 B0 = pack2(bl.x, bl.y), B1p = pack2(bl.z, bl.w);
        u64 B2 = pack2(bh.x, bh.y), B3 = pack2(bh.z, bh.w);
        u64 A0 = pack2(a.x, a.x), A1 = pack2(a.y, a.y);
        u64 A2 = pack2(a.z, a.z), A3 = pack2(a.w, a.w);
        fma2(acc2[0][0], A0, B0); fma2(acc2[0][1], A0, B1p); fma2(acc2[0][2], A0, B2); fma2(acc2[0][3], A0, B3);
        fma2(acc2[1][0], A1, B0); fma2(acc2[1][1], A1, B1p); fma2(acc2[1][2], A1, B2); fma2(acc2[1][3], A1, B3);
        fma2(acc2[2][0], A2, B0); fma2(acc2[2][1], A2, B1p); fma2(acc2[2][2], A2, B2); fma2(acc2[2][3], A2, B3);
        fma2(acc2[3][0], A3, B0); fma2(acc2[3][1], A3, B1p); fma2(acc2[3][2], A3, B2); fma2(acc2[3][3], A3, B3);
    }
    __syncthreads();  // Hs reads done; reuse as Os[128][68]

    float* Os = Hs;
#pragma unroll
    for (int u = 0; u < 4; u++) {
        float vals[8];
#pragma unroll
        for (int p = 0; p < 4; p++) unpack2(vals[2 * p], vals[2 * p + 1], acc2[u][p]);
#pragma unroll
        for (int q = 0; q < 8; q++) {
            int qq = (q + tj) & 7;
            int j = jb + qq;
            Os[(nb + u) * 68 + j] = fmaxf(vals[qq] + cst[192 + j], 0.f);
        }
    }
    __syncthreads();

    // write out
    {
        int n = tid >> 1, h = tid & 1;
        int node = base + n;
        if (node < N) {
#pragma unroll
            for (int i = 0; i < 8; i++) {
                float4 vv = *(const float4*)(Os + n * 68 + h * 32 + i * 4);
                *(float4*)(g_x + (size_t)node * 64 + h * 32 + i * 4) = vv;
            }
        }
    }

    // pooling
    if (tid < 64) {
        int rows = min(128, N - base);
        float* pool = g_pooled + (size_t)poolIdx * (MAXG * HDIM);
        int cur = __ldg(&batch[base]);
        float s = 0.f;
        for (int r = 0; r < rows; r++) {
            int b = __ldg(&batch[base + r]);
            if (b != cur) { atomicAdd(&pool[cur * 64 + tid], s); s = 0.f; cur = b; }
            s += Os[r * 68 + tid];
        }
        atomicAdd(&pool[cur * 64 + tid], s);
    }
}

// ---------------- final: per-graph logits + softmax ----------------
__global__ void k_final(const float* __restrict__ lin_W, const float* __restrict__ lin_b,
                        float* __restrict__ out, int G)
{
    int g = threadIdx.x;
    if (g >= G) return;
    double l0 = 0.0, l1 = 0.0;
    for (int p = 0; p < 4; p++) {
        const float* pw = lin_W + p * 128;
        const float* pv = g_pooled + (size_t)p * (MAXG * HDIM) + g * 64;
        for (int k = 0; k < 64; k++) {
            float v = pv[k];
            l0 += (double)v * pw[k * 2 + 0];
            l1 += (double)v * pw[k * 2 + 1];
        }
    }
    double c = (double)g_cnt[g];
    l0 += c * lin_b[0] + lin_b[2] + lin_b[4] + lin_b[6];
    l1 += c * lin_b[1] + lin_b[3] + lin_b[5] + lin_b[7];
    float f0 = (float)l0, f1 = (float)l1;
    float m = fmaxf(f0, f1);
    float e0 = expf(f0 - m), e1 = expf(f1 - m);
    float inv = 1.f / (e0 + e1);
    out[g * 2 + 0] = e0 * inv;
    out[g * 2 + 1] = e1 * inv;
}

// ---------------- launch ----------------
extern "C" void kernel_launch(void* const* d_in, const int* in_sizes, int n_in,
                              void* d_out, int out_size)
{
    const int*   node_ids = (const int*)d_in[0];
    const int*   edge     = (const int*)d_in[1];
    const int*   batch    = (const int*)d_in[2];
    const float* emb      = (const float*)d_in[3];
    const float* fh_W1 = (const float*)d_in[4];
    const float* fh_b1 = (const float*)d_in[5];
    const float* fh_g1 = (const float*)d_in[6];
    const float* fh_bt1 = (const float*)d_in[7];
    const float* fh_m1 = (const float*)d_in[8];
    const float* fh_v1 = (const float*)d_in[9];
    const float* fh_W2 = (const float*)d_in[10];
    const float* fh_b2 = (const float*)d_in[11];
    const float* fh_g2 = (const float*)d_in[12];
    const float* fh_bt2 = (const float*)d_in[13];
    const float* fh_m2 = (const float*)d_in[14];
    const float* fh_v2 = (const float*)d_in[15];
    const float* conv_W1 = (const float*)d_in[16];
    const float* conv_b1 = (const float*)d_in[17];
    const float* conv_g1 = (const float*)d_in[18];
    const float* conv_bt1 = (const float*)d_in[19];
    const float* conv_m1 = (const float*)d_in[20];
    const float* conv_v1 = (const float*)d_in[21];
    const float* conv_W2 = (const float*)d_in[22];
    const float* conv_b2 = (const float*)d_in[23];
    const float* conv_g2 = (const float*)d_in[24];
    const float* conv_bt2 = (const float*)d_in[25];
    const float* conv_m2 = (const float*)d_in[26];
    const float* conv_v2 = (const float*)d_in[27];
    const float* lin_W = (const float*)d_in[28];
    const float* lin_b = (const float*)d_in[29];

    int N = in_sizes[0];
    int E = in_sizes[1] / 2;
    int G = out_size / 2;
    const int* src = edge;
    const int* dst = edge + E;

    const int SMEM_EMB  = (128 * 64 + 64 * 64 + 128 * 68 + 64 * 68 + 256) * 4;    // 102400
    const int SMEM_CONV = (64 * 64 + 64 * 64 + 64 * 132 + 8704 + 256) * 4;        // 101888
    cudaFuncSetAttribute((const void*)k_mlp_embed,
                         cudaFuncAttributeMaxDynamicSharedMemorySize, SMEM_EMB);
    cudaFuncSetAttribute((const void*)k_conv,
                         cudaFuncAttributeMaxDynamicSharedMemorySize, SMEM_CONV);

    int zn = (4 * MAXG * HDIM > N + 1) ? 4 * MAXG * HDIM : N + 1;

    // 1: zero accumulators / counters
    k_zero<<<(zn + 255) / 256, 256>>>(N + 1);
    // 2: degree + graph-size counts
    k_count<<<(E + 255) / 256, 256>>>(dst, batch, E, N);
    // 3: scan phase 1
    int nb = (N + 1023) / 1024;
    k_scan1<<<nb, 1024>>>(N);
    // 4: embed MLP (independent of CSR) — placed here so ncu's capture window hits it
    k_mlp_embed<<<(N + 63) / 64, 256, SMEM_EMB>>>(
        emb, node_ids,
        fh_W1, fh_b1, fh_g1, fh_bt1, fh_m1, fh_v1,
        fh_W2, fh_b2, fh_g2, fh_bt2, fh_m2, fh_v2,
        batch, N);
    // 5-7: finish CSR build
    k_scan2<<<1, 1024>>>(nb);
    k_scan3<<<(N + 255) / 256, 256>>>(N, nb);
    k_fill<<<(E + 255) / 256, 256>>>(src, dst, E);

    // 8-10: fused conv layers (gather + MLP + pool)
    int cblocks = (N + 127) / 128;
    for (int l = 0; l < 3; l++) {
        k_conv<<<cblocks, 256, SMEM_CONV>>>(
            conv_W1 + l * 4096, conv_b1 + l * 64, conv_g1 + l * 64, conv_bt1 + l * 64,
            conv_m1 + l * 64, conv_v1 + l * 64,
            conv_W2 + l * 4096, conv_b2 + l * 64, conv_g2 + l * 64, conv_bt2 + l * 64,
            conv_m2 + l * 64, conv_v2 + l * 64,
            batch, l + 1, N);
    }

    // 11: readout
    k_final<<<1, 128>>>(lin_W, lin_b, (float*)d_out, G);
}

// round 12
// speedup vs baseline: 1.3671x; 1.3671x over previous
#include <cuda_runtime.h>
#include <math.h>

#define MAXN 100000
#define MAXE 1000000
#define MAXG 128
#define HDIM 64

typedef unsigned long long u64;

// ---------------- f32x2 packed helpers ----------------
__device__ __forceinline__ u64 pack2(float lo, float hi) {
    u64 r; asm("mov.b64 %0, {%1, %2};" : "=l"(r) : "f"(lo), "f"(hi)); return r;
}
__device__ __forceinline__ void unpack2(float& lo, float& hi, u64 v) {
    asm("mov.b64 {%0, %1}, %2;" : "=f"(lo), "=f"(hi) : "l"(v));
}
__device__ __forceinline__ void fma2(u64& acc, u64 a, u64 b) {
    asm("fma.rn.f32x2 %0, %1, %2, %0;" : "+l"(acc) : "l"(a), "l"(b));
}

// ---------------- device scratch ----------------
__device__ float g_x[MAXN * HDIM];
__device__ float g_t[MAXN * HDIM];
__device__ int   g_indeg[MAXN + 1];
__device__ int   g_off[MAXN + 1];
__device__ int   g_cursor[MAXN];
__device__ int   g_csr[MAXE];
__device__ int   g_bsum[1024];
__device__ float g_pooled[4 * MAXG * HDIM];
__device__ int   g_cnt[MAXG];

// ---------------- small kernels ----------------
__global__ void k_zero(int n_indeg) {
    int i = blockIdx.x * blockDim.x + threadIdx.x;
    if (i < 4 * MAXG * HDIM) g_pooled[i] = 0.f;
    if (i < MAXG) g_cnt[i] = 0;
    if (i < n_indeg) g_indeg[i] = 0;
}

__global__ void k_count(const int* __restrict__ dst, const int* __restrict__ batch,
                        int E, int N) {
    int e = blockIdx.x * blockDim.x + threadIdx.x;
    if (e < E) atomicAdd(&g_indeg[dst[e]], 1);
    if (e < N) atomicAdd(&g_cnt[batch[e]], 1);
}

__global__ void k_scan1(int n) {
    __shared__ int s[1024];
    int i = blockIdx.x * 1024 + threadIdx.x;
    int v = (i < n) ? g_indeg[i] : 0;
    s[threadIdx.x] = v; __syncthreads();
    for (int d = 1; d < 1024; d <<= 1) {
        int t = (threadIdx.x >= d) ? s[threadIdx.x - d] : 0;
        __syncthreads(); s[threadIdx.x] += t; __syncthreads();
    }
    if (i < n) g_cursor[i] = s[threadIdx.x];
    if (threadIdx.x == 1023) g_bsum[blockIdx.x] = s[1023];
}
__global__ void k_scan2(int nb) {
    __shared__ int s[1024];
    int v = (threadIdx.x < nb) ? g_bsum[threadIdx.x] : 0;
    s[threadIdx.x] = v; __syncthreads();
    for (int d = 1; d < 1024; d <<= 1) {
        int t = (threadIdx.x >= d) ? s[threadIdx.x - d] : 0;
        __syncthreads(); s[threadIdx.x] += t; __syncthreads();
    }
    if (threadIdx.x < nb) g_bsum[threadIdx.x] = s[threadIdx.x];
}
__global__ void k_scan3(int n, int nb) {
    int i = blockIdx.x * blockDim.x + threadIdx.x;
    if (i < n) {
        int blk = i >> 10;
        int pref = (blk > 0) ? g_bsum[blk - 1] : 0;
        int excl = g_cursor[i] - g_indeg[i] + pref;
        g_off[i] = excl; g_cursor[i] = excl;
    }
    if (i == 0) g_off[n] = g_bsum[nb - 1];
}
__global__ void k_fill(const int* __restrict__ src, const int* __restrict__ dst, int E) {
    int e = blockIdx.x * blockDim.x + threadIdx.x;
    if (e < E) { int pos = atomicAdd(&g_cursor[dst[e]], 1); g_csr[pos] = src[e]; }
}

// ---------------- aggregation: g_t[n] = g_x[n] + sum_{src->n} g_x[src] ----------------
__global__ void k_agg(int N) {
    int w = (blockIdx.x * blockDim.x + threadIdx.x) >> 5;
    int lane = threadIdx.x & 31;
    if (w >= N) return;
    const float2* xb = (const float2*)g_x;
    float2 acc = xb[(size_t)w * 32 + lane];
    int s = g_off[w], e = g_off[w + 1];
    for (int i = s; i < e; i++) {
        int sn = __ldg(&g_csr[i]);
        float2 v = __ldg(&xb[(size_t)sn * 32 + lane]);
        acc.x += v.x; acc.y += v.y;
    }
    ((float2*)g_t)[(size_t)w * 32 + lane] = acc;
}

// ---------------- fused 2-layer MLP (BN folded) + sum-pool ----------------
// 256 threads, 64-node x 64-out tile, 4x4 micro-tile (FFMA2).
// Layer-1 K dim processed in CHUNKS chunks of 64 (reusing W1s/Xs buffers) so
// smem stays at 68.6KB -> 3 blocks/SM for BOTH embed (IN=128) and conv (IN=64).
template <int CHUNKS, bool EMBED>
__global__ void __launch_bounds__(256) k_mlp(
    const float* __restrict__ emb, const int* __restrict__ node_ids,
    const float* __restrict__ W1, const float* __restrict__ B1,
    const float* __restrict__ G1, const float* __restrict__ BT1,
    const float* __restrict__ M1, const float* __restrict__ V1,
    const float* __restrict__ W2, const float* __restrict__ B2,
    const float* __restrict__ G2, const float* __restrict__ BT2,
    const float* __restrict__ M2, const float* __restrict__ V2,
    const int* __restrict__ batch, int poolIdx, int N)
{
    extern __shared__ float sm[];
    float* W1s = sm;                 // 64*64 (per-chunk)
    float* W2s = W1s + 64 * 64;      // 64*64
    float* Xs  = W2s + 64 * 64;      // 64*68 (per-chunk, transposed [k][node])
    float* Hs  = Xs + 64 * 68;       // 64*68
    float* cst = Hs + 64 * 68;       // sc1, of1, sc2, of2

    int tid = threadIdx.x;
    int base = blockIdx.x * 64;
    int n4 = tid >> 2, q4 = tid & 3;
    int node4 = base + n4;

    if (tid < 64) {
        float s = G1[tid] * rsqrtf(V1[tid] + 1e-5f);
        cst[tid] = s;
        cst[64 + tid] = B1[tid] * s + BT1[tid] - M1[tid] * s;
        float s2 = G2[tid] * rsqrtf(V2[tid] + 1e-5f);
        cst[128 + tid] = s2;
        cst[192 + tid] = B2[tid] * s2 + BT2[tid] - M2[tid] * s2;
    }
    __syncthreads();

    for (int i = tid; i < 64 * 64; i += 256) W2s[i] = W2[i] * cst[128 + (i & 63)];

    const float4* row4 = 0;
    if (EMBED) {
        int nid = (node4 < N) ? __ldg(&node_ids[node4]) : 0;
        row4 = (const float4*)(emb + (size_t)nid * 128);
    } else {
        row4 = (const float4*)(g_t + (size_t)node4 * 64);
    }

    int tj = tid & 15, tn = tid >> 4;
    int nb = tn * 4, jb = tj * 4;
    u64 acc2[4][2];
#pragma unroll
    for (int u = 0; u < 4; u++) { acc2[u][0] = 0ULL; acc2[u][1] = 0ULL; }

    // ---- layer 1 over K chunks ----
    for (int c = 0; c < CHUNKS; c++) {
        // stage W1 chunk (BN-scaled) + X chunk
        for (int i = tid; i < 64 * 64; i += 256) W1s[i] = W1[c * 4096 + i] * cst[i & 63];
#pragma unroll
        for (int i = 0; i < 4; i++) {
            float4 v = make_float4(0.f, 0.f, 0.f, 0.f);
            if (node4 < N) v = __ldg(&row4[c * 16 + q4 * 4 + i]);
            int k = (q4 * 4 + i) * 4;
            Xs[(k + 0) * 68 + n4] = v.x;
            Xs[(k + 1) * 68 + n4] = v.y;
            Xs[(k + 2) * 68 + n4] = v.z;
            Xs[(k + 3) * 68 + n4] = v.w;
        }
        __syncthreads();
#pragma unroll 4
        for (int k = 0; k < 64; k++) {
            float4 a = *(const float4*)(Xs + k * 68 + nb);
            float4 b = *(const float4*)(W1s + k * 64 + jb);
            u64 b0 = pack2(b.x, b.y), b1 = pack2(b.z, b.w);
            u64 a0 = pack2(a.x, a.x), a1 = pack2(a.y, a.y);
            u64 a2 = pack2(a.z, a.z), a3 = pack2(a.w, a.w);
            fma2(acc2[0][0], a0, b0); fma2(acc2[0][1], a0, b1);
            fma2(acc2[1][0], a1, b0); fma2(acc2[1][1], a1, b1);
            fma2(acc2[2][0], a2, b0); fma2(acc2[2][1], a2, b1);
            fma2(acc2[3][0], a3, b0); fma2(acc2[3][1], a3, b1);
        }
        __syncthreads();
    }

    // epilogue 1: add folded offset + ReLU -> Hs[j][n]
#pragma unroll
    for (int p = 0; p < 2; p++) {
        float o0 = cst[64 + jb + 2 * p], o1 = cst[64 + jb + 2 * p + 1];
#pragma unroll
        for (int u = 0; u < 4; u++) {
            float lo, hi;
            unpack2(lo, hi, acc2[u][p]);
            Hs[(jb + 2 * p) * 68 + nb + u]     = fmaxf(lo + o0, 0.f);
            Hs[(jb + 2 * p + 1) * 68 + nb + u] = fmaxf(hi + o1, 0.f);
            acc2[u][p] = 0ULL;
        }
    }
    __syncthreads();

    // ---- layer 2 ----
#pragma unroll 4
    for (int k = 0; k < 64; k++) {
        float4 a = *(const float4*)(Hs + k * 68 + nb);
        float4 b = *(const float4*)(W2s + k * 64 + jb);
        u64 b0 = pack2(b.x, b.y), b1 = pack2(b.z, b.w);
        u64 a0 = pack2(a.x, a.x), a1 = pack2(a.y, a.y);
        u64 a2 = pack2(a.z, a.z), a3 = pack2(a.w, a.w);
        fma2(acc2[0][0], a0, b0); fma2(acc2[0][1], a0, b1);
        fma2(acc2[1][0], a1, b0); fma2(acc2[1][1], a1, b1);
        fma2(acc2[2][0], a2, b0); fma2(acc2[2][1], a2, b1);
        fma2(acc2[3][0], a3, b0); fma2(acc2[3][1], a3, b1);
    }
    __syncthreads();  // Hs reads done; reuse as Os[n][j]

    float* Os = Hs;
#pragma unroll
    for (int p = 0; p < 2; p++) {
        float o0 = cst[192 + jb + 2 * p], o1 = cst[192 + jb + 2 * p + 1];
#pragma unroll
        for (int u = 0; u < 4; u++) {
            float lo, hi;
            unpack2(lo, hi, acc2[u][p]);
            Os[(nb + u) * 68 + jb + 2 * p]     = fmaxf(lo + o0, 0.f);
            Os[(nb + u) * 68 + jb + 2 * p + 1] = fmaxf(hi + o1, 0.f);
        }
    }
    __syncthreads();

    // write out coalesced
    if (node4 < N) {
#pragma unroll
        for (int i = 0; i < 4; i++) {
            float4 vv = *(const float4*)(Os + n4 * 68 + q4 * 16 + i * 4);
            *(float4*)(g_x + (size_t)node4 * 64 + q4 * 16 + i * 4) = vv;
        }
    }

    // pooling: sorted-batch running-sum flush
    if (tid < 64) {
        int rows = min(64, N - base);
        float* pool = g_pooled + (size_t)poolIdx * (MAXG * HDIM);
        int cur = __ldg(&batch[base]);
        float s = 0.f;
        for (int r = 0; r < rows; r++) {
            int b = __ldg(&batch[base + r]);
            if (b != cur) { atomicAdd(&pool[cur * 64 + tid], s); s = 0.f; cur = b; }
            s += Os[r * 68 + tid];
        }
        atomicAdd(&pool[cur * 64 + tid], s);
    }
}

// ---------------- final: per-graph logits + softmax ----------------
__global__ void k_final(const float* __restrict__ lin_W, const float* __restrict__ lin_b,
                        float* __restrict__ out, int G)
{
    int g = threadIdx.x;
    if (g >= G) return;
    double l0 = 0.0, l1 = 0.0;
    for (int p = 0; p < 4; p++) {
        const float* pw = lin_W + p * 128;
        const float* pv = g_pooled + (size_t)p * (MAXG * HDIM) + g * 64;
        for (int k = 0; k < 64; k++) {
            float v = pv[k];
            l0 += (double)v * pw[k * 2 + 0];
            l1 += (double)v * pw[k * 2 + 1];
        }
    }
    double c = (double)g_cnt[g];
    l0 += c * lin_b[0] + lin_b[2] + lin_b[4] + lin_b[6];
    l1 += c * lin_b[1] + lin_b[3] + lin_b[5] + lin_b[7];
    float f0 = (float)l0, f1 = (float)l1;
    float m = fmaxf(f0, f1);
    float e0 = expf(f0 - m), e1 = expf(f1 - m);
    float inv = 1.f / (e0 + e1);
    out[g * 2 + 0] = e0 * inv;
    out[g * 2 + 1] = e1 * inv;
}

// ---------------- launch ----------------
extern "C" void kernel_launch(void* const* d_in, const int* in_sizes, int n_in,
                              void* d_out, int out_size)
{
    const int*   node_ids = (const int*)d_in[0];
    const int*   edge     = (const int*)d_in[1];
    const int*   batch    = (const int*)d_in[2];
    const float* emb      = (const float*)d_in[3];
    const float* fh_W1 = (const float*)d_in[4];
    const float* fh_b1 = (const float*)d_in[5];
    const float* fh_g1 = (const float*)d_in[6];
    const float* fh_bt1 = (const float*)d_in[7];
    const float* fh_m1 = (const float*)d_in[8];
    const float* fh_v1 = (const float*)d_in[9];
    const float* fh_W2 = (const float*)d_in[10];
    const float* fh_b2 = (const float*)d_in[11];
    const float* fh_g2 = (const float*)d_in[12];
    const float* fh_bt2 = (const float*)d_in[13];
    const float* fh_m2 = (const float*)d_in[14];
    const float* fh_v2 = (const float*)d_in[15];
    const float* conv_W1 = (const float*)d_in[16];
    const float* conv_b1 = (const float*)d_in[17];
    const float* conv_g1 = (const float*)d_in[18];
    const float* conv_bt1 = (const float*)d_in[19];
    const float* conv_m1 = (const float*)d_in[20];
    const float* conv_v1 = (const float*)d_in[21];
    const float* conv_W2 = (const float*)d_in[22];
    const float* conv_b2 = (const float*)d_in[23];
    const float* conv_g2 = (const float*)d_in[24];
    const float* conv_bt2 = (const float*)d_in[25];
    const float* conv_m2 = (const float*)d_in[26];
    const float* conv_v2 = (const float*)d_in[27];
    const float* lin_W = (const float*)d_in[28];
    const float* lin_b = (const float*)d_in[29];

    int N = in_sizes[0];
    int E = in_sizes[1] / 2;
    int G = out_size / 2;
    const int* src = edge;
    const int* dst = edge + E;

    const int SMEM_MLP = (64 * 64 + 64 * 64 + 64 * 68 + 64 * 68 + 256) * 4;  // 68608
    cudaFuncSetAttribute((const void*)k_mlp<2, true>,
                         cudaFuncAttributeMaxDynamicSharedMemorySize, SMEM_MLP);
    cudaFuncSetAttribute((const void*)k_mlp<1, false>,
                         cudaFuncAttributeMaxDynamicSharedMemorySize, SMEM_MLP);

    int zn = (4 * MAXG * HDIM > N + 1) ? 4 * MAXG * HDIM : N + 1;

    // zero + counts
    k_zero<<<(zn + 255) / 256, 256>>>(N + 1);
    k_count<<<(E + 255) / 256, 256>>>(dst, batch, E, N);
    // scan phase 1
    int nb = (N + 1023) / 1024;
    k_scan1<<<nb, 1024>>>(N);
    // embed MLP (independent of CSR) — kept early for ncu capture-window visibility
    int mblocks = (N + 63) / 64;
    k_mlp<2, true><<<mblocks, 256, SMEM_MLP>>>(
        emb, node_ids,
        fh_W1, fh_b1, fh_g1, fh_bt1, fh_m1, fh_v1,
        fh_W2, fh_b2, fh_g2, fh_bt2, fh_m2, fh_v2,
        batch, 0, N);
    // finish CSR build
    k_scan2<<<1, 1024>>>(nb);
    k_scan3<<<(N + 255) / 256, 256>>>(N, nb);
    k_fill<<<(E + 255) / 256, 256>>>(src, dst, E);

    // 3 GINConv layers: warp-per-node gather, then MLP
    for (int l = 0; l < 3; l++) {
        k_agg<<<(N + 7) / 8, 256>>>(N);
        k_mlp<1, false><<<mblocks, 256, SMEM_MLP>>>(
            nullptr, nullptr,
            conv_W1 + l * 4096, conv_b1 + l * 64, conv_g1 + l * 64, conv_bt1 + l * 64,
            conv_m1 + l * 64, conv_v1 + l * 64,
            conv_W2 + l * 4096, conv_b2 + l * 64, conv_g2 + l * 64, conv_bt2 + l * 64,
            conv_m2 + l * 64, conv_v2 + l * 64,
            batch, l + 1, N);
    }

    k_final<<<1, 128>>>(lin_W, lin_b, (float*)d_out, G);
}

// round 13
// speedup vs baseline: 1.3989x; 1.0232x over previous
#include <cuda_runtime.h>
#include <math.h>

#define MAXN 100000
#define MAXE 1000000
#define MAXG 128
#define HDIM 64

typedef unsigned long long u64;

// ---------------- f32x2 packed helpers ----------------
__device__ __forceinline__ u64 pack2(float lo, float hi) {
    u64 r; asm("mov.b64 %0, {%1, %2};" : "=l"(r) : "f"(lo), "f"(hi)); return r;
}
__device__ __forceinline__ void unpack2(float& lo, float& hi, u64 v) {
    asm("mov.b64 {%0, %1}, %2;" : "=f"(lo), "=f"(hi) : "l"(v));
}
__device__ __forceinline__ void fma2(u64& acc, u64 a, u64 b) {
    asm("fma.rn.f32x2 %0, %1, %2, %0;" : "+l"(acc) : "l"(a), "l"(b));
}

// ---------------- device scratch ----------------
__device__ float g_x[MAXN * HDIM];
__device__ float g_t[MAXN * HDIM];
__device__ int   g_indeg[MAXN + 1];
__device__ int   g_off[MAXN + 1];
__device__ int   g_cursor[MAXN];
__device__ int   g_csr[MAXE];
__device__ int   g_bsum[1024];
__device__ float g_pooled[4 * MAXG * HDIM];
__device__ int   g_cnt[MAXG];

// ---------------- small kernels ----------------
__global__ void k_zero(int n_indeg) {
    int i = blockIdx.x * blockDim.x + threadIdx.x;
    if (i < 4 * MAXG * HDIM) g_pooled[i] = 0.f;
    if (i < MAXG) g_cnt[i] = 0;
    if (i < n_indeg) g_indeg[i] = 0;
}

__global__ void k_count(const int* __restrict__ dst, const int* __restrict__ batch,
                        int E, int N) {
    int e = blockIdx.x * blockDim.x + threadIdx.x;
    if (e < E) atomicAdd(&g_indeg[dst[e]], 1);
    if (e < N) atomicAdd(&g_cnt[batch[e]], 1);
}

__global__ void k_scan1(int n) {
    __shared__ int s[1024];
    int i = blockIdx.x * 1024 + threadIdx.x;
    int v = (i < n) ? g_indeg[i] : 0;
    s[threadIdx.x] = v; __syncthreads();
    for (int d = 1; d < 1024; d <<= 1) {
        int t = (threadIdx.x >= d) ? s[threadIdx.x - d] : 0;
        __syncthreads(); s[threadIdx.x] += t; __syncthreads();
    }
    if (i < n) g_cursor[i] = s[threadIdx.x];
    if (threadIdx.x == 1023) g_bsum[blockIdx.x] = s[1023];
}
__global__ void k_scan2(int nb) {
    __shared__ int s[1024];
    int v = (threadIdx.x < nb) ? g_bsum[threadIdx.x] : 0;
    s[threadIdx.x] = v; __syncthreads();
    for (int d = 1; d < 1024; d <<= 1) {
        int t = (threadIdx.x >= d) ? s[threadIdx.x - d] : 0;
        __syncthreads(); s[threadIdx.x] += t; __syncthreads();
    }
    if (threadIdx.x < nb) g_bsum[threadIdx.x] = s[threadIdx.x];
}
__global__ void k_scan3(int n, int nb) {
    int i = blockIdx.x * blockDim.x + threadIdx.x;
    if (i < n) {
        int blk = i >> 10;
        int pref = (blk > 0) ? g_bsum[blk - 1] : 0;
        int excl = g_cursor[i] - g_indeg[i] + pref;
        g_off[i] = excl; g_cursor[i] = excl;
    }
    if (i == 0) g_off[n] = g_bsum[nb - 1];
}
__global__ void k_fill(const int* __restrict__ src, const int* __restrict__ dst, int E) {
    int e = blockIdx.x * blockDim.x + threadIdx.x;
    if (e < E) { int pos = atomicAdd(&g_cursor[dst[e]], 1); g_csr[pos] = src[e]; }
}

// ---------------- aggregation: g_t[n] = g_x[n] + sum_{src->n} g_x[src] ----------------
__global__ void k_agg(int N) {
    int w = (blockIdx.x * blockDim.x + threadIdx.x) >> 5;
    int lane = threadIdx.x & 31;
    if (w >= N) return;
    const float2* xb = (const float2*)g_x;
    float2 acc = xb[(size_t)w * 32 + lane];
    int s = g_off[w], e = g_off[w + 1];
    for (int i = s; i < e; i++) {
        int sn = __ldg(&g_csr[i]);
        float2 v = __ldg(&xb[(size_t)sn * 32 + lane]);
        acc.x += v.x; acc.y += v.y;
    }
    ((float2*)g_t)[(size_t)w * 32 + lane] = acc;
}

// ---------------- fused 2-layer MLP, 8x8 micro-tile (FFMA2), BN folded ----------------
// 128 threads, tile 128 nodes x 64 outs; per-thread 8 nodes x 8 outs.
// Single 16KB weight buffer restaged (W1 chunks, then W2) to keep smem at 87KB.
// Smem layout (floats): Ws[4096] | Xs[64*136] | Hs[64*136] | cst[256]
// Xs buffer is reused as Os[128*68] for the output tile.
template <int CHUNKS, bool EMBED>
__global__ void __launch_bounds__(128) k_mlp(
    const float* __restrict__ emb, const int* __restrict__ node_ids,
    const float* __restrict__ W1, const float* __restrict__ B1,
    const float* __restrict__ G1, const float* __restrict__ BT1,
    const float* __restrict__ M1, const float* __restrict__ V1,
    const float* __restrict__ W2, const float* __restrict__ B2,
    const float* __restrict__ G2, const float* __restrict__ BT2,
    const float* __restrict__ M2, const float* __restrict__ V2,
    const int* __restrict__ batch, int poolIdx, int N)
{
    extern __shared__ float sm[];
    float* Ws  = sm;                       // 4096
    float* Xs  = sm + 4096;                // 64 x 136
    float* Hs  = sm + 4096 + 8704;         // 64 x 136
    float* cst = sm + 4096 + 2 * 8704;     // 256

    int tid = threadIdx.x;
    int base = blockIdx.x * 128;
    int node = base + tid;
    bool valid = node < N;

    if (tid < 64) {
        float s = G1[tid] * rsqrtf(V1[tid] + 1e-5f);
        cst[tid] = s;
        cst[64 + tid] = B1[tid] * s + BT1[tid] - M1[tid] * s;
        float s2 = G2[tid] * rsqrtf(V2[tid] + 1e-5f);
        cst[128 + tid] = s2;
        cst[192 + tid] = B2[tid] * s2 + BT2[tid] - M2[tid] * s2;
    }
    __syncthreads();

    const float4* row4;
    if (EMBED) {
        int nid = valid ? __ldg(&node_ids[node]) : 0;
        row4 = (const float4*)(emb + (size_t)nid * 128);
    } else {
        row4 = (const float4*)(g_t + (size_t)node * 64);
    }

    int tj = tid & 7, tn = tid >> 3;
    int nb = tn * 8, jb = tj * 8;
    // acc[p][j]: nodes (nb+2p, nb+2p+1), output jb+j
    u64 acc[4][8];
#pragma unroll
    for (int p = 0; p < 4; p++)
#pragma unroll
        for (int j = 0; j < 8; j++) acc[p][j] = 0ULL;

    // ---- layer 1 over K chunks of 64 ----
    for (int c = 0; c < CHUNKS; c++) {
        for (int i = tid; i < 4096; i += 128) Ws[i] = W1[c * 4096 + i] * cst[i & 63];
        // stage this thread's node row chunk, transposed Xs[k][node]
#pragma unroll
        for (int i = 0; i < 16; i++) {
            float4 v = make_float4(0.f, 0.f, 0.f, 0.f);
            if (valid) v = __ldg(&row4[c * 16 + i]);
            int k = i * 4;
            Xs[(k + 0) * 136 + tid] = v.x;
            Xs[(k + 1) * 136 + tid] = v.y;
            Xs[(k + 2) * 136 + tid] = v.z;
            Xs[(k + 3) * 136 + tid] = v.w;
        }
        __syncthreads();
#pragma unroll 2
        for (int k = 0; k < 64; k++) {
            float4 a0 = *(const float4*)(Xs + k * 136 + nb);
            float4 a1 = *(const float4*)(Xs + k * 136 + nb + 4);
            float4 b0 = *(const float4*)(Ws + k * 64 + jb);
            float4 b1 = *(const float4*)(Ws + k * 64 + jb + 4);
            u64 A0 = pack2(a0.x, a0.y), A1 = pack2(a0.z, a0.w);
            u64 A2 = pack2(a1.x, a1.y), A3 = pack2(a1.z, a1.w);
            u64 Bd[8] = { pack2(b0.x, b0.x), pack2(b0.y, b0.y),
                          pack2(b0.z, b0.z), pack2(b0.w, b0.w),
                          pack2(b1.x, b1.x), pack2(b1.y, b1.y),
                          pack2(b1.z, b1.z), pack2(b1.w, b1.w) };
#pragma unroll
            for (int j = 0; j < 8; j++) {
                fma2(acc[0][j], A0, Bd[j]);
                fma2(acc[1][j], A1, Bd[j]);
                fma2(acc[2][j], A2, Bd[j]);
                fma2(acc[3][j], A3, Bd[j]);
            }
        }
        __syncthreads();
    }

    // epilogue 1: +offset, ReLU -> Hs[j][n] (pairs contiguous -> STS.64)
#pragma unroll
    for (int j = 0; j < 8; j++) {
        float o = cst[64 + jb + j];
#pragma unroll
        for (int p = 0; p < 4; p++) {
            float lo, hi;
            unpack2(lo, hi, acc[p][j]);
            lo = fmaxf(lo + o, 0.f); hi = fmaxf(hi + o, 0.f);
            *(float2*)(Hs + (jb + j) * 136 + nb + 2 * p) = make_float2(lo, hi);
            acc[p][j] = 0ULL;
        }
    }
    // restage W2 (scaled) into the same weight buffer
    for (int i = tid; i < 4096; i += 128) Ws[i] = W2[i] * cst[128 + (i & 63)];
    __syncthreads();

    // ---- layer 2 ----
#pragma unroll 2
    for (int k = 0; k < 64; k++) {
        float4 a0 = *(const float4*)(Hs + k * 136 + nb);
        float4 a1 = *(const float4*)(Hs + k * 136 + nb + 4);
        float4 b0 = *(const float4*)(Ws + k * 64 + jb);
        float4 b1 = *(const float4*)(Ws + k * 64 + jb + 4);
        u64 A0 = pack2(a0.x, a0.y), A1 = pack2(a0.z, a0.w);
        u64 A2 = pack2(a1.x, a1.y), A3 = pack2(a1.z, a1.w);
        u64 Bd[8] = { pack2(b0.x, b0.x), pack2(b0.y, b0.y),
                      pack2(b0.z, b0.z), pack2(b0.w, b0.w),
                      pack2(b1.x, b1.x), pack2(b1.y, b1.y),
                      pack2(b1.z, b1.z), pack2(b1.w, b1.w) };
#pragma unroll
        for (int j = 0; j < 8; j++) {
            fma2(acc[0][j], A0, Bd[j]);
            fma2(acc[1][j], A1, Bd[j]);
            fma2(acc[2][j], A2, Bd[j]);
            fma2(acc[3][j], A3, Bd[j]);
        }
    }
    // final epilogue -> Os[n][j] (Os reuses the Xs buffer; Xs is dead)
    float* Os = Xs;
#pragma unroll
    for (int j = 0; j < 8; j++) {
        float o = cst[192 + jb + j];
#pragma unroll
        for (int p = 0; p < 4; p++) {
            float lo, hi;
            unpack2(lo, hi, acc[p][j]);
            Os[(nb + 2 * p) * 68 + jb + j]     = fmaxf(lo + o, 0.f);
            Os[(nb + 2 * p + 1) * 68 + jb + j] = fmaxf(hi + o, 0.f);
        }
    }
    __syncthreads();

    // write out coalesced: thread = node
    if (valid) {
#pragma unroll
        for (int i = 0; i < 16; i++) {
            float4 vv = *(const float4*)(Os + tid * 68 + i * 4);
            *(float4*)(g_x + (size_t)node * 64 + i * 4) = vv;
        }
    }

    // pooling: sorted-batch running-sum flush over 128 rows
    if (tid < 64) {
        int rows = min(128, N - base);
        float* pool = g_pooled + (size_t)poolIdx * (MAXG * HDIM);
        int cur = __ldg(&batch[base]);
        float s = 0.f;
        for (int r = 0; r < rows; r++) {
            int b = __ldg(&batch[base + r]);
            if (b != cur) { atomicAdd(&pool[cur * 64 + tid], s); s = 0.f; cur = b; }
            s += Os[r * 68 + tid];
        }
        atomicAdd(&pool[cur * 64 + tid], s);
    }
}

// ---------------- final: per-graph logits + softmax ----------------
__global__ void k_final(const float* __restrict__ lin_W, const float* __restrict__ lin_b,
                        float* __restrict__ out, int G)
{
    int g = threadIdx.x;
    if (g >= G) return;
    double l0 = 0.0, l1 = 0.0;
    for (int p = 0; p < 4; p++) {
        const float* pw = lin_W + p * 128;
        const float* pv = g_pooled + (size_t)p * (MAXG * HDIM) + g * 64;
        for (int k = 0; k < 64; k++) {
            float v = pv[k];
            l0 += (double)v * pw[k * 2 + 0];
            l1 += (double)v * pw[k * 2 + 1];
        }
    }
    double c = (double)g_cnt[g];
    l0 += c * lin_b[0] + lin_b[2] + lin_b[4] + lin_b[6];
    l1 += c * lin_b[1] + lin_b[3] + lin_b[5] + lin_b[7];
    float f0 = (float)l0, f1 = (float)l1;
    float m = fmaxf(f0, f1);
    float e0 = expf(f0 - m), e1 = expf(f1 - m);
    float inv = 1.f / (e0 + e1);
    out[g * 2 + 0] = e0 * inv;
    out[g * 2 + 1] = e1 * inv;
}

// ---------------- launch ----------------
extern "C" void kernel_launch(void* const* d_in, const int* in_sizes, int n_in,
                              void* d_out, int out_size)
{
    const int*   node_ids = (const int*)d_in[0];
    const int*   edge     = (const int*)d_in[1];
    const int*   batch    = (const int*)d_in[2];
    const float* emb      = (const float*)d_in[3];
    const float* fh_W1 = (const float*)d_in[4];
    const float* fh_b1 = (const float*)d_in[5];
    const float* fh_g1 = (const float*)d_in[6];
    const float* fh_bt1 = (const float*)d_in[7];
    const float* fh_m1 = (const float*)d_in[8];
    const float* fh_v1 = (const float*)d_in[9];
    const float* fh_W2 = (const float*)d_in[10];
    const float* fh_b2 = (const float*)d_in[11];
    const float* fh_g2 = (const float*)d_in[12];
    const float* fh_bt2 = (const float*)d_in[13];
    const float* fh_m2 = (const float*)d_in[14];
    const float* fh_v2 = (const float*)d_in[15];
    const float* conv_W1 = (const float*)d_in[16];
    const float* conv_b1 = (const float*)d_in[17];
    const float* conv_g1 = (const float*)d_in[18];
    const float* conv_bt1 = (const float*)d_in[19];
    const float* conv_m1 = (const float*)d_in[20];
    const float* conv_v1 = (const float*)d_in[21];
    const float* conv_W2 = (const float*)d_in[22];
    const float* conv_b2 = (const float*)d_in[23];
    const float* conv_g2 = (const float*)d_in[24];
    const float* conv_bt2 = (const float*)d_in[25];
    const float* conv_m2 = (const float*)d_in[26];
    const float* conv_v2 = (const float*)d_in[27];
    const float* lin_W = (const float*)d_in[28];
    const float* lin_b = (const float*)d_in[29];

    int N = in_sizes[0];
    int E = in_sizes[1] / 2;
    int G = out_size / 2;
    const int* src = edge;
    const int* dst = edge + E;

    const int SMEM_MLP = (4096 + 2 * 8704 + 256) * 4;  // 87040 bytes
    cudaFuncSetAttribute((const void*)k_mlp<2, true>,
                         cudaFuncAttributeMaxDynamicSharedMemorySize, SMEM_MLP);
    cudaFuncSetAttribute((const void*)k_mlp<1, false>,
                         cudaFuncAttributeMaxDynamicSharedMemorySize, SMEM_MLP);

    int zn = (4 * MAXG * HDIM > N + 1) ? 4 * MAXG * HDIM : N + 1;

    // zero + counts
    k_zero<<<(zn + 255) / 256, 256>>>(N + 1);
    k_count<<<(E + 255) / 256, 256>>>(dst, batch, E, N);
    // scan phase 1
    int nb = (N + 1023) / 1024;
    k_scan1<<<nb, 1024>>>(N);
    // embed MLP (independent of CSR) — early for ncu capture-window visibility
    int mblocks = (N + 127) / 128;
    k_mlp<2, true><<<mblocks, 128, SMEM_MLP>>>(
        emb, node_ids,
        fh_W1, fh_b1, fh_g1, fh_bt1, fh_m1, fh_v1,
        fh_W2, fh_b2, fh_g2, fh_bt2, fh_m2, fh_v2,
        batch, 0, N);
    // finish CSR build
    k_scan2<<<1, 1024>>>(nb);
    k_scan3<<<(N + 255) / 256, 256>>>(N, nb);
    k_fill<<<(E + 255) / 256, 256>>>(src, dst, E);

    // 3 GINConv layers: warp-per-node gather, then MLP
    for (int l = 0; l < 3; l++) {
        k_agg<<<(N + 7) / 8, 256>>>(N);
        k_mlp<1, false><<<mblocks, 128, SMEM_MLP>>>(
            nullptr, nullptr,
            conv_W1 + l * 4096, conv_b1 + l * 64, conv_g1 + l * 64, conv_bt1 + l * 64,
            conv_m1 + l * 64, conv_v1 + l * 64,
            conv_W2 + l * 4096, conv_b2 + l * 64, conv_g2 + l * 64, conv_bt2 + l * 64,
            conv_m2 + l * 64, conv_v2 + l * 64,
            batch, l + 1, N);
    }

    k_final<<<1, 128>>>(lin_W, lin_b, (float*)d_out, G);
}

// round 14
// speedup vs baseline: 1.5500x; 1.1081x over previous
#include <cuda_runtime.h>
#include <math.h>

#define MAXN 100000
#define MAXE 1000000
#define MAXG 128
#define HDIM 64

typedef unsigned long long u64;

// ---------------- f32x2 packed helpers ----------------
__device__ __forceinline__ u64 pack2(float lo, float hi) {
    u64 r; asm("mov.b64 %0, {%1, %2};" : "=l"(r) : "f"(lo), "f"(hi)); return r;
}
__device__ __forceinline__ void unpack2(float& lo, float& hi, u64 v) {
    asm("mov.b64 {%0, %1}, %2;" : "=f"(lo), "=f"(hi) : "l"(v));
}
__device__ __forceinline__ void fma2(u64& acc, u64 a, u64 b) {
    asm("fma.rn.f32x2 %0, %1, %2, %0;" : "+l"(acc) : "l"(a), "l"(b));
}

// ---------------- device scratch ----------------
__device__ float g_x[MAXN * HDIM];
__device__ float g_t[MAXN * HDIM];
__device__ int   g_indeg[MAXN + 1];
__device__ int   g_off[MAXN + 1];
__device__ int   g_cursor[MAXN];
__device__ int   g_csr[MAXE];
__device__ int   g_bsum[1024];
__device__ float g_pooled[4 * MAXG * HDIM];
__device__ int   g_cnt[MAXG];

// ---------------- small kernels ----------------
__global__ void k_zero(int n_indeg) {
    int i = blockIdx.x * blockDim.x + threadIdx.x;
    if (i < 4 * MAXG * HDIM) g_pooled[i] = 0.f;
    if (i < MAXG) g_cnt[i] = 0;
    if (i < n_indeg) g_indeg[i] = 0;
}

__global__ void k_count(const int* __restrict__ dst, const int* __restrict__ batch,
                        int E, int N) {
    int e = blockIdx.x * blockDim.x + threadIdx.x;
    if (e < E) atomicAdd(&g_indeg[dst[e]], 1);
    if (e < N) atomicAdd(&g_cnt[batch[e]], 1);
}

__global__ void k_scan1(int n) {
    __shared__ int s[1024];
    int i = blockIdx.x * 1024 + threadIdx.x;
    int v = (i < n) ? g_indeg[i] : 0;
    s[threadIdx.x] = v; __syncthreads();
    for (int d = 1; d < 1024; d <<= 1) {
        int t = (threadIdx.x >= d) ? s[threadIdx.x - d] : 0;
        __syncthreads(); s[threadIdx.x] += t; __syncthreads();
    }
    if (i < n) g_cursor[i] = s[threadIdx.x];
    if (threadIdx.x == 1023) g_bsum[blockIdx.x] = s[1023];
}
__global__ void k_scan2(int nb) {
    __shared__ int s[1024];
    int v = (threadIdx.x < nb) ? g_bsum[threadIdx.x] : 0;
    s[threadIdx.x] = v; __syncthreads();
    for (int d = 1; d < 1024; d <<= 1) {
        int t = (threadIdx.x >= d) ? s[threadIdx.x - d] : 0;
        __syncthreads(); s[threadIdx.x] += t; __syncthreads();
    }
    if (threadIdx.x < nb) g_bsum[threadIdx.x] = s[threadIdx.x];
}
__global__ void k_scan3(int n, int nb) {
    int i = blockIdx.x * blockDim.x + threadIdx.x;
    if (i < n) {
        int blk = i >> 10;
        int pref = (blk > 0) ? g_bsum[blk - 1] : 0;
        int excl = g_cursor[i] - g_indeg[i] + pref;
        g_off[i] = excl; g_cursor[i] = excl;
    }
    if (i == 0) g_off[n] = g_bsum[nb - 1];
}
__global__ void k_fill(const int* __restrict__ src, const int* __restrict__ dst, int E) {
    int e = blockIdx.x * blockDim.x + threadIdx.x;
    if (e < E) { int pos = atomicAdd(&g_cursor[dst[e]], 1); g_csr[pos] = src[e]; }
}

// ---------------- aggregation: g_t[n] = g_x[n] + sum_{src->n} g_x[src] ----------------
__global__ void k_agg(int N) {
    int w = (blockIdx.x * blockDim.x + threadIdx.x) >> 5;
    int lane = threadIdx.x & 31;
    if (w >= N) return;
    const float2* xb = (const float2*)g_x;
    float2 acc = xb[(size_t)w * 32 + lane];
    int s = g_off[w], e = g_off[w + 1];
    for (int i = s; i < e; i++) {
        int sn = __ldg(&g_csr[i]);
        float2 v = __ldg(&xb[(size_t)sn * 32 + lane]);
        acc.x += v.x; acc.y += v.y;
    }
    ((float2*)g_t)[(size_t)w * 32 + lane] = acc;
}

// ---------------- fused 2-layer MLP, 8x8 micro-tile (FFMA2), BN folded ----------------
// 128 threads, tile 128 nodes x 64 outs; per-thread 8 nodes x 8 outs.
// X and H share ONE 34.8KB buffer (X dead after layer-1 k-loop), weights share
// one 16KB buffer (restaged W1 chunks -> W2). Smem 52.2KB -> 4 blocks/SM.
// Smem layout (floats): Ws[4096] | XH[64*136] | cst[256]
template <int CHUNKS, bool EMBED>
__global__ void __launch_bounds__(128, 4) k_mlp(
    const float* __restrict__ emb, const int* __restrict__ node_ids,
    const float* __restrict__ W1, const float* __restrict__ B1,
    const float* __restrict__ G1, const float* __restrict__ BT1,
    const float* __restrict__ M1, const float* __restrict__ V1,
    const float* __restrict__ W2, const float* __restrict__ B2,
    const float* __restrict__ G2, const float* __restrict__ BT2,
    const float* __restrict__ M2, const float* __restrict__ V2,
    const int* __restrict__ batch, int poolIdx, int N)
{
    extern __shared__ float sm[];
    float* Ws  = sm;                 // 4096
    float* XH  = sm + 4096;          // 64 x 136 (X per chunk, then H, then Os)
    float* cst = sm + 4096 + 8704;   // 256

    int tid = threadIdx.x;
    int base = blockIdx.x * 128;
    int node = base + tid;
    bool valid = node < N;

    if (tid < 64) {
        float s = G1[tid] * rsqrtf(V1[tid] + 1e-5f);
        cst[tid] = s;
        cst[64 + tid] = B1[tid] * s + BT1[tid] - M1[tid] * s;
        float s2 = G2[tid] * rsqrtf(V2[tid] + 1e-5f);
        cst[128 + tid] = s2;
        cst[192 + tid] = B2[tid] * s2 + BT2[tid] - M2[tid] * s2;
    }
    __syncthreads();

    const float4* row4;
    if (EMBED) {
        int nid = valid ? __ldg(&node_ids[node]) : 0;
        row4 = (const float4*)(emb + (size_t)nid * 128);
    } else {
        row4 = (const float4*)(g_t + (size_t)node * 64);
    }

    int tj = tid & 7, tn = tid >> 3;
    int nb = tn * 8, jb = tj * 8;
    // acc[p][j]: node pair (nb+2p, nb+2p+1), output jb+j
    u64 acc[4][8];
#pragma unroll
    for (int p = 0; p < 4; p++)
#pragma unroll
        for (int j = 0; j < 8; j++) acc[p][j] = 0ULL;

    // ---- layer 1 over K chunks of 64 ----
    for (int c = 0; c < CHUNKS; c++) {
        for (int i = tid; i < 4096; i += 128) Ws[i] = W1[c * 4096 + i] * cst[i & 63];
        // stage this thread's node row chunk, transposed XH[k][node]
#pragma unroll
        for (int i = 0; i < 16; i++) {
            float4 v = make_float4(0.f, 0.f, 0.f, 0.f);
            if (valid) v = __ldg(&row4[c * 16 + i]);
            int k = i * 4;
            XH[(k + 0) * 136 + tid] = v.x;
            XH[(k + 1) * 136 + tid] = v.y;
            XH[(k + 2) * 136 + tid] = v.z;
            XH[(k + 3) * 136 + tid] = v.w;
        }
        __syncthreads();
#pragma unroll 2
        for (int k = 0; k < 64; k++) {
            float4 a0 = *(const float4*)(XH + k * 136 + nb);
            float4 a1 = *(const float4*)(XH + k * 136 + nb + 4);
            float4 b0 = *(const float4*)(Ws + k * 64 + jb);
            float4 b1 = *(const float4*)(Ws + k * 64 + jb + 4);
            u64 A0 = pack2(a0.x, a0.y), A1 = pack2(a0.z, a0.w);
            u64 A2 = pack2(a1.x, a1.y), A3 = pack2(a1.z, a1.w);
            u64 Bd[8] = { pack2(b0.x, b0.x), pack2(b0.y, b0.y),
                          pack2(b0.z, b0.z), pack2(b0.w, b0.w),
                          pack2(b1.x, b1.x), pack2(b1.y, b1.y),
                          pack2(b1.z, b1.z), pack2(b1.w, b1.w) };
#pragma unroll
            for (int j = 0; j < 8; j++) {
                fma2(acc[0][j], A0, Bd[j]);
                fma2(acc[1][j], A1, Bd[j]);
                fma2(acc[2][j], A2, Bd[j]);
                fma2(acc[3][j], A3, Bd[j]);
            }
        }
        __syncthreads();   // X reads done (and Ws reads done) before overwrite
    }

    // epilogue 1: +offset, ReLU -> H[j][n] written into the XH buffer
#pragma unroll
    for (int j = 0; j < 8; j++) {
        float o = cst[64 + jb + j];
#pragma unroll
        for (int p = 0; p < 4; p++) {
            float lo, hi;
            unpack2(lo, hi, acc[p][j]);
            lo = fmaxf(lo + o, 0.f); hi = fmaxf(hi + o, 0.f);
            *(float2*)(XH + (jb + j) * 136 + nb + 2 * p) = make_float2(lo, hi);
            acc[p][j] = 0ULL;
        }
    }
    // restage W2 (scaled) into the same weight buffer
    for (int i = tid; i < 4096; i += 128) Ws[i] = W2[i] * cst[128 + (i & 63)];
    __syncthreads();

    // ---- layer 2 ----
#pragma unroll 2
    for (int k = 0; k < 64; k++) {
        float4 a0 = *(const float4*)(XH + k * 136 + nb);
        float4 a1 = *(const float4*)(XH + k * 136 + nb + 4);
        float4 b0 = *(const float4*)(Ws + k * 64 + jb);
        float4 b1 = *(const float4*)(Ws + k * 64 + jb + 4);
        u64 A0 = pack2(a0.x, a0.y), A1 = pack2(a0.z, a0.w);
        u64 A2 = pack2(a1.x, a1.y), A3 = pack2(a1.z, a1.w);
        u64 Bd[8] = { pack2(b0.x, b0.x), pack2(b0.y, b0.y),
                      pack2(b0.z, b0.z), pack2(b0.w, b0.w),
                      pack2(b1.x, b1.x), pack2(b1.y, b1.y),
                      pack2(b1.z, b1.z), pack2(b1.w, b1.w) };
#pragma unroll
        for (int j = 0; j < 8; j++) {
            fma2(acc[0][j], A0, Bd[j]);
            fma2(acc[1][j], A1, Bd[j]);
            fma2(acc[2][j], A2, Bd[j]);
            fma2(acc[3][j], A3, Bd[j]);
        }
    }
    __syncthreads();   // H reads done; reuse XH as Os[n][j] (128 x 68)

    float* Os = XH;
#pragma unroll
    for (int j = 0; j < 8; j++) {
        float o = cst[192 + jb + j];
#pragma unroll
        for (int p = 0; p < 4; p++) {
            float lo, hi;
            unpack2(lo, hi, acc[p][j]);
            Os[(nb + 2 * p) * 68 + jb + j]     = fmaxf(lo + o, 0.f);
            Os[(nb + 2 * p + 1) * 68 + jb + j] = fmaxf(hi + o, 0.f);
        }
    }
    __syncthreads();

    // write out coalesced: thread = node
    if (valid) {
#pragma unroll
        for (int i = 0; i < 16; i++) {
            float4 vv = *(const float4*)(Os + tid * 68 + i * 4);
            *(float4*)(g_x + (size_t)node * 64 + i * 4) = vv;
        }
    }

    // pooling: sorted-batch running-sum flush over 128 rows
    if (tid < 64) {
        int rows = min(128, N - base);
        float* pool = g_pooled + (size_t)poolIdx * (MAXG * HDIM);
        int cur = __ldg(&batch[base]);
        float s = 0.f;
        for (int r = 0; r < rows; r++) {
            int b = __ldg(&batch[base + r]);
            if (b != cur) { atomicAdd(&pool[cur * 64 + tid], s); s = 0.f; cur = b; }
            s += Os[r * 68 + tid];
        }
        atomicAdd(&pool[cur * 64 + tid], s);
    }
}

// ---------------- final: per-graph logits + softmax ----------------
__global__ void k_final(const float* __restrict__ lin_W, const float* __restrict__ lin_b,
                        float* __restrict__ out, int G)
{
    int g = threadIdx.x;
    if (g >= G) return;
    double l0 = 0.0, l1 = 0.0;
    for (int p = 0; p < 4; p++) {
        const float* pw = lin_W + p * 128;
        const float* pv = g_pooled + (size_t)p * (MAXG * HDIM) + g * 64;
        for (int k = 0; k < 64; k++) {
            float v = pv[k];
            l0 += (double)v * pw[k * 2 + 0];
            l1 += (double)v * pw[k * 2 + 1];
        }
    }
    double c = (double)g_cnt[g];
    l0 += c * lin_b[0] + lin_b[2] + lin_b[4] + lin_b[6];
    l1 += c * lin_b[1] + lin_b[3] + lin_b[5] + lin_b[7];
    float f0 = (float)l0, f1 = (float)l1;
    float m = fmaxf(f0, f1);
    float e0 = expf(f0 - m), e1 = expf(f1 - m);
    float inv = 1.f / (e0 + e1);
    out[g * 2 + 0] = e0 * inv;
    out[g * 2 + 1] = e1 * inv;
}

// ---------------- launch ----------------
extern "C" void kernel_launch(void* const* d_in, const int* in_sizes, int n_in,
                              void* d_out, int out_size)
{
    const int*   node_ids = (const int*)d_in[0];
    const int*   edge     = (const int*)d_in[1];
    const int*   batch    = (const int*)d_in[2];
    const float* emb      = (const float*)d_in[3];
    const float* fh_W1 = (const float*)d_in[4];
    const float* fh_b1 = (const float*)d_in[5];
    const float* fh_g1 = (const float*)d_in[6];
    const float* fh_bt1 = (const float*)d_in[7];
    const float* fh_m1 = (const float*)d_in[8];
    const float* fh_v1 = (const float*)d_in[9];
    const float* fh_W2 = (const float*)d_in[10];
    const float* fh_b2 = (const float*)d_in[11];
    const float* fh_g2 = (const float*)d_in[12];
    const float* fh_bt2 = (const float*)d_in[13];
    const float* fh_m2 = (const float*)d_in[14];
    const float* fh_v2 = (const float*)d_in[15];
    const float* conv_W1 = (const float*)d_in[16];
    const float* conv_b1 = (const float*)d_in[17];
    const float* conv_g1 = (const float*)d_in[18];
    const float* conv_bt1 = (const float*)d_in[19];
    const float* conv_m1 = (const float*)d_in[20];
    const float* conv_v1 = (const float*)d_in[21];
    const float* conv_W2 = (const float*)d_in[22];
    const float* conv_b2 = (const float*)d_in[23];
    const float* conv_g2 = (const float*)d_in[24];
    const float* conv_bt2 = (const float*)d_in[25];
    const float* conv_m2 = (const float*)d_in[26];
    const float* conv_v2 = (const float*)d_in[27];
    const float* lin_W = (const float*)d_in[28];
    const float* lin_b = (const float*)d_in[29];

    int N = in_sizes[0];
    int E = in_sizes[1] / 2;
    int G = out_size / 2;
    const int* src = edge;
    const int* dst = edge + E;

    const int SMEM_MLP = (4096 + 8704 + 256) * 4;  // 52224 bytes -> 4 blocks/SM
    cudaFuncSetAttribute((const void*)k_mlp<2, true>,
                         cudaFuncAttributeMaxDynamicSharedMemorySize, SMEM_MLP);
    cudaFuncSetAttribute((const void*)k_mlp<1, false>,
                         cudaFuncAttributeMaxDynamicSharedMemorySize, SMEM_MLP);

    int zn = (4 * MAXG * HDIM > N + 1) ? 4 * MAXG * HDIM : N + 1;

    // zero + counts
    k_zero<<<(zn + 255) / 256, 256>>>(N + 1);
    k_count<<<(E + 255) / 256, 256>>>(dst, batch, E, N);
    // scan phase 1
    int nb = (N + 1023) / 1024;
    k_scan1<<<nb, 1024>>>(N);
    // embed MLP (independent of CSR) — early for ncu capture-window visibility
    int mblocks = (N + 127) / 128;
    k_mlp<2, true><<<mblocks, 128, SMEM_MLP>>>(
        emb, node_ids,
        fh_W1, fh_b1, fh_g1, fh_bt1, fh_m1, fh_v1,
        fh_W2, fh_b2, fh_g2, fh_bt2, fh_m2, fh_v2,
        batch, 0, N);
    // finish CSR build
    k_scan2<<<1, 1024>>>(nb);
    k_scan3<<<(N + 255) / 256, 256>>>(N, nb);
    k_fill<<<(E + 255) / 256, 256>>>(src, dst, E);

    // 3 GINConv layers: warp-per-node gather, then MLP
    for (int l = 0; l < 3; l++) {
        k_agg<<<(N + 7) / 8, 256>>>(N);
        k_mlp<1, false><<<mblocks, 128, SMEM_MLP>>>(
            nullptr, nullptr,
            conv_W1 + l * 4096, conv_b1 + l * 64, conv_g1 + l * 64, conv_bt1 + l * 64,
            conv_m1 + l * 64, conv_v1 + l * 64,
            conv_W2 + l * 4096, conv_b2 + l * 64, conv_g2 + l * 64, conv_bt2 + l * 64,
            conv_m2 + l * 64, conv_v2 + l * 64,
            batch, l + 1, N);
    }

    k_final<<<1, 128>>>(lin_W, lin_b, (float*)d_out, G);
}